// round 6
// baseline (speedup 1.0000x reference)
#include <cuda_runtime.h>
#include <cuda_bf16.h>
#include <cstdint>

#define NN 50000
#define EE 800000
#define EPP 200000
#define DIM 128
#define KK 256
#define MTILES ((NN + 127) / 128)

// ---------------- scratch ----------------------------------------------------
__device__ int   g_deg[NN];
__device__ int   g_rowptr[NN + 1];
__device__ int   g_cursor[NN];
__device__ int   g_csr_src[EE];
__device__ float g_h[NN * DIM];
__device__ float g_z[NN * DIM];
__device__ __nv_bfloat16 g_Ahi[NN * KK];      // [node][k]  k<128: agg, k>=128: feat
__device__ __nv_bfloat16 g_Alo[NN * KK];
__device__ __nv_bfloat16 g_Whi[2 * DIM * KK]; // [layer][n][k]  (Wcat transposed)
__device__ __nv_bfloat16 g_Wlo[2 * DIM * KK];

__device__ __forceinline__ uint32_t smem_u32(const void* p) {
    uint32_t a;
    asm("{ .reg .u64 t; cvta.to.shared.u64 t, %1; cvt.u32.u64 %0, t; }" : "=r"(a) : "l"(p));
    return a;
}

// split fp32 -> bf16 hi + bf16 lo, packed stores
__device__ __forceinline__ void split_store4(float4 v, __nv_bfloat16* hp, __nv_bfloat16* lp) {
    __nv_bfloat162 h0 = __floats2bfloat162_rn(v.x, v.y);
    __nv_bfloat162 h1 = __floats2bfloat162_rn(v.z, v.w);
    float lx = v.x - __bfloat162float(h0.x);
    float ly = v.y - __bfloat162float(h0.y);
    float lz = v.z - __bfloat162float(h1.x);
    float lw = v.w - __bfloat162float(h1.y);
    __nv_bfloat162 l0 = __floats2bfloat162_rn(lx, ly);
    __nv_bfloat162 l1 = __floats2bfloat162_rn(lz, lw);
    *(uint2*)hp = make_uint2(*(unsigned*)&h0, *(unsigned*)&h1);
    *(uint2*)lp = make_uint2(*(unsigned*)&l0, *(unsigned*)&l1);
}
__device__ __forceinline__ void split_store2(float a, float b, __nv_bfloat16* hp, __nv_bfloat16* lp) {
    __nv_bfloat162 h = __floats2bfloat162_rn(a, b);
    float la = a - __bfloat162float(h.x);
    float lb = b - __bfloat162float(h.y);
    __nv_bfloat162 l = __floats2bfloat162_rn(la, lb);
    *(unsigned*)hp = *(unsigned*)&h;
    *(unsigned*)lp = *(unsigned*)&l;
}

// ---------------- CSR build --------------------------------------------------
__global__ void k_zero_deg() {
    int i = blockIdx.x * blockDim.x + threadIdx.x;
    if (i < NN) g_deg[i] = 0;
}
// 4 edges per thread (EE % 4 == 0)
__global__ void k_count(const int* __restrict__ dst) {
    int q = blockIdx.x * blockDim.x + threadIdx.x;
    if (q >= EE / 4) return;
    int4 d4 = ((const int4*)dst)[q];
    unsigned d0 = (unsigned)d4.x, d1 = (unsigned)d4.y,
             d2 = (unsigned)d4.z, d3 = (unsigned)d4.w;
    if (d0 < NN) atomicAdd(&g_deg[d0], 1);
    if (d1 < NN) atomicAdd(&g_deg[d1], 1);
    if (d2 < NN) atomicAdd(&g_deg[d2], 1);
    if (d3 < NN) atomicAdd(&g_deg[d3], 1);
}
__global__ void k_scan() {
    __shared__ int warp_sums[32];
    __shared__ int s_carry;
    int tid = threadIdx.x;
    if (tid == 0) s_carry = 0;
    __syncthreads();
    for (int base = 0; base < NN; base += 1024) {
        int i = base + tid;
        int v = (i < NN) ? g_deg[i] : 0;
        int x = v;
        #pragma unroll
        for (int o = 1; o < 32; o <<= 1) {
            int y = __shfl_up_sync(0xffffffffu, x, o);
            if ((tid & 31) >= o) x += y;
        }
        if ((tid & 31) == 31) warp_sums[tid >> 5] = x;
        __syncthreads();
        if (tid < 32) {
            int w = warp_sums[tid];
            #pragma unroll
            for (int o = 1; o < 32; o <<= 1) {
                int y = __shfl_up_sync(0xffffffffu, w, o);
                if (tid >= o) w += y;
            }
            warp_sums[tid] = w;
        }
        __syncthreads();
        int incl = x + ((tid >= 32) ? warp_sums[(tid >> 5) - 1] : 0) + s_carry;
        if (i < NN) {
            g_rowptr[i + 1] = incl;
            g_cursor[i] = incl - v;
        }
        __syncthreads();
        if (tid == 1023) s_carry = incl;
        __syncthreads();
    }
    if (tid == 0) g_rowptr[0] = 0;
}
// 4 edges per thread
__global__ void k_fill(const int* __restrict__ src, const int* __restrict__ dst) {
    int q = blockIdx.x * blockDim.x + threadIdx.x;
    if (q >= EE / 4) return;
    int4 d4 = ((const int4*)dst)[q];
    int4 s4 = ((const int4*)src)[q];
    #pragma unroll
    for (int j = 0; j < 4; ++j) {
        unsigned d = (unsigned)(&d4.x)[j];
        unsigned s = (unsigned)(&s4.x)[j];
        if (d < NN && s < NN) {
            int p = atomicAdd(&g_cursor[d], 1);
            if ((unsigned)p < EE) g_csr_src[p] = (int)s;
        }
    }
}

// ---------------- weight prepack: Wcat^T split to bf16 hi/lo -----------------
__global__ void k_prepackW(const float* __restrict__ W1l, const float* __restrict__ W1r,
                           const float* __restrict__ W2l, const float* __restrict__ W2r) {
    int idx = blockIdx.x * blockDim.x + threadIdx.x;
    if (idx >= 2 * DIM * KK) return;
    int l = idx / (DIM * KK);
    int rem = idx - l * (DIM * KK);
    int n = rem / KK, k = rem % KK;
    const float* Wl = l ? W2l : W1l;
    const float* Wr = l ? W2r : W1r;
    float w = (k < DIM) ? Wl[k * DIM + n] : Wr[(k - DIM) * DIM + n];
    __nv_bfloat16 hi = __float2bfloat16(w);
    __nv_bfloat16 lo = __float2bfloat16(w - __bfloat162float(hi));
    g_Whi[idx] = hi;
    g_Wlo[idx] = lo;
}

// ---------------- mean aggregation (warp per node, MLP=4) --------------------
__global__ void k_agg(const float* __restrict__ feat_in, int use_h) {
    const float* feat = use_h ? g_h : feat_in;
    int warp_id = (blockIdx.x * blockDim.x + threadIdx.x) >> 5;
    int lane = threadIdx.x & 31;
    if (warp_id >= NN) return;
    int n = warp_id;
    int start = g_rowptr[n], end = g_rowptr[n + 1];
    const float4* f4 = (const float4*)feat;
    float4 a0 = make_float4(0.f, 0.f, 0.f, 0.f);
    float4 a1 = a0, a2 = a0, a3 = a0;
    for (int base = start; base < end; base += 32) {
        int m = min(32, end - base);
        int sid = (lane < m) ? g_csr_src[base + lane] : 0;
        int t = 0;
        for (; t + 4 <= m; t += 4) {
            int s0 = __shfl_sync(0xffffffffu, sid, t);
            int s1 = __shfl_sync(0xffffffffu, sid, t + 1);
            int s2 = __shfl_sync(0xffffffffu, sid, t + 2);
            int s3 = __shfl_sync(0xffffffffu, sid, t + 3);
            float4 v0 = f4[(size_t)s0 * 32 + lane];
            float4 v1 = f4[(size_t)s1 * 32 + lane];
            float4 v2 = f4[(size_t)s2 * 32 + lane];
            float4 v3 = f4[(size_t)s3 * 32 + lane];
            a0.x += v0.x; a0.y += v0.y; a0.z += v0.z; a0.w += v0.w;
            a1.x += v1.x; a1.y += v1.y; a1.z += v1.z; a1.w += v1.w;
            a2.x += v2.x; a2.y += v2.y; a2.z += v2.z; a2.w += v2.w;
            a3.x += v3.x; a3.y += v3.y; a3.z += v3.z; a3.w += v3.w;
        }
        for (; t < m; ++t) {
            int s = __shfl_sync(0xffffffffu, sid, t);
            float4 v = f4[(size_t)s * 32 + lane];
            a0.x += v.x; a0.y += v.y; a0.z += v.z; a0.w += v.w;
        }
    }
    a0.x += a1.x + a2.x + a3.x;
    a0.y += a1.y + a2.y + a3.y;
    a0.z += a1.z + a2.z + a3.z;
    a0.w += a1.w + a2.w + a3.w;
    int d = end - start;
    float inv = 1.0f / (float)max(d, 1);
    a0.x *= inv; a0.y *= inv; a0.z *= inv; a0.w *= inv;
    size_t off = (size_t)n * KK + lane * 4;
    split_store4(a0, &g_Ahi[off], &g_Alo[off]);
    if (!use_h) {  // layer 1: also split own feature x[n] into A[:,128:256]
        float4 v = f4[(size_t)n * 32 + lane];
        size_t o2 = (size_t)n * KK + DIM + lane * 4;
        split_store4(v, &g_Ahi[o2], &g_Alo[o2]);
    }
}

// ---------------- bf16-split GEMM via mma.sync + ldmatrix --------------------
#define SMEM_MM 65536
#define T_AH 0
#define T_AL 16384
#define T_WH 32768
#define T_WL 49152

__device__ __forceinline__ void ldsm_x4(uint32_t r[4], uint32_t saddr) {
    asm volatile("ldmatrix.sync.aligned.m8n8.x4.shared.b16 {%0,%1,%2,%3}, [%4];"
                 : "=r"(r[0]), "=r"(r[1]), "=r"(r[2]), "=r"(r[3]) : "r"(saddr));
}

#define MMA_BF16(d, a, b0, b1)                                                    \
    asm volatile("mma.sync.aligned.m16n8k16.row.col.f32.bf16.bf16.f32 "           \
                 "{%0,%1,%2,%3}, {%4,%5,%6,%7}, {%8,%9}, {%0,%1,%2,%3};"          \
                 : "+f"((d)[0]), "+f"((d)[1]), "+f"((d)[2]), "+f"((d)[3])         \
                 : "r"((a)[0]), "r"((a)[1]), "r"((a)[2]), "r"((a)[3]),            \
                   "r"(b0), "r"(b1))

__global__ void __launch_bounds__(256) k_mm(const float* __restrict__ bias, int layer) {
    extern __shared__ char smem[];
    uint32_t sb = smem_u32(smem);
    int tid = threadIdx.x, w = tid >> 5, l = tid & 31;
    int row0 = blockIdx.x * 128;
    const __nv_bfloat16* Wh = g_Whi + (layer - 1) * DIM * KK;
    const __nv_bfloat16* Wl = g_Wlo + (layer - 1) * DIM * KK;

    float acc[16][4];
    #pragma unroll
    for (int i = 0; i < 16; ++i)
        acc[i][0] = acc[i][1] = acc[i][2] = acc[i][3] = 0.f;

    int rA = w * 16 + (l & 7) + ((l >> 3) & 1) * 8;
    int uA_lane = (l >> 4) & 1;
    int rB_lane = (l & 7) + ((l >> 4) & 1) * 8;
    int uB_lane = (l >> 3) & 1;
    uint32_t aA_base = sb + (uint32_t)(rA * 128);
    int swA = (rA & 7);

    for (int chunk = 0; chunk < 4; ++chunk) {
        for (int i = tid; i < 4096; i += 256) {
            int t = i >> 10, s = i & 1023;
            int r = s >> 3, u4 = s & 7;
            uint4 v = make_uint4(0, 0, 0, 0);
            if (t < 2) {
                int gr = row0 + r;
                if (gr < NN) {
                    const __nv_bfloat16* p =
                        (t == 0 ? g_Ahi : g_Alo) + (size_t)gr * KK + chunk * 64 + u4 * 8;
                    v = *(const uint4*)p;
                }
            } else {
                const __nv_bfloat16* p =
                    (t == 2 ? Wh : Wl) + (size_t)r * KK + chunk * 64 + u4 * 8;
                v = *(const uint4*)p;
            }
            *(uint4*)(smem + t * 16384 + r * 128 + ((u4 ^ (r & 7)) << 4)) = v;
        }
        __syncthreads();

        #pragma unroll
        for (int ks = 0; ks < 4; ++ks) {
            int uA = ks * 2 + uA_lane;
            uint32_t ah[4], al[4];
            ldsm_x4(ah, aA_base + T_AH + (uint32_t)((uA ^ swA) << 4));
            ldsm_x4(al, aA_base + T_AL + (uint32_t)((uA ^ swA) << 4));
            int uB = ks * 2 + uB_lane;
            #pragma unroll
            for (int p = 0; p < 8; ++p) {
                int rB = p * 16 + rB_lane;
                uint32_t off = (uint32_t)(rB * 128 + (((uB ^ (rB & 7))) << 4));
                uint32_t bh[4], bl[4];
                ldsm_x4(bh, sb + T_WH + off);
                ldsm_x4(bl, sb + T_WL + off);
                MMA_BF16(acc[2 * p], ah, bh[0], bh[1]);
                MMA_BF16(acc[2 * p], al, bh[0], bh[1]);
                MMA_BF16(acc[2 * p], ah, bl[0], bl[1]);
                MMA_BF16(acc[2 * p + 1], ah, bh[2], bh[3]);
                MMA_BF16(acc[2 * p + 1], al, bh[2], bh[3]);
                MMA_BF16(acc[2 * p + 1], ah, bl[2], bl[3]);
            }
        }
        __syncthreads();
    }

    float* outp = (layer == 1) ? g_h : g_z;
    int r1 = row0 + w * 16 + (l >> 2);
    int r2 = r1 + 8;
    #pragma unroll
    for (int nt = 0; nt < 16; ++nt) {
        int c = nt * 8 + (l & 3) * 2;
        float2 b2 = *(const float2*)&bias[c];
        float* d = acc[nt];
        float v0 = d[0] + b2.x, v1 = d[1] + b2.y;
        float v2 = d[2] + b2.x, v3 = d[3] + b2.y;
        if (layer == 1) {
            v0 = fmaxf(v0, 0.f); v1 = fmaxf(v1, 0.f);
            v2 = fmaxf(v2, 0.f); v3 = fmaxf(v3, 0.f);
        }
        if (r1 < NN) {
            *(float2*)&outp[(size_t)r1 * DIM + c] = make_float2(v0, v1);
            if (layer == 1) {
                size_t o = (size_t)r1 * KK + DIM + c;
                split_store2(v0, v1, &g_Ahi[o], &g_Alo[o]);
            }
        }
        if (r2 < NN) {
            *(float2*)&outp[(size_t)r2 * DIM + c] = make_float2(v2, v3);
            if (layer == 1) {
                size_t o = (size_t)r2 * KK + DIM + c;
                split_store2(v2, v3, &g_Ahi[o], &g_Alo[o]);
            }
        }
    }
}

// ---------------- link prediction (warp per pred edge) -----------------------
__global__ void k_pred(const int* __restrict__ ps, const int* __restrict__ pd,
                       float* __restrict__ out) {
    int warp_id = (blockIdx.x * blockDim.x + threadIdx.x) >> 5;
    int lane = threadIdx.x & 31;
    if (warp_id >= EPP) return;
    const float4* z4 = (const float4*)g_z;
    unsigned a = (unsigned)ps[warp_id], b = (unsigned)pd[warp_id];
    if (a >= NN) a = 0;
    if (b >= NN) b = 0;
    float4 u = z4[(size_t)a * 32 + lane];
    float4 v = z4[(size_t)b * 32 + lane];
    float d = u.x * v.x + u.y * v.y + u.z * v.z + u.w * v.w;
    #pragma unroll
    for (int o = 16; o > 0; o >>= 1) d += __shfl_xor_sync(0xffffffffu, d, o);
    if (lane == 0) out[warp_id] = d;
}

// ---------------- launch -----------------------------------------------------
extern "C" void kernel_launch(void* const* d_in, const int* in_sizes, int n_in,
                              void* d_out, int out_size) {
    const float* x   = (const float*)d_in[0];
    const float* W1l = (const float*)d_in[1];
    const float* b1  = (const float*)d_in[2];
    const float* W1r = (const float*)d_in[3];
    const float* W2l = (const float*)d_in[4];
    const float* b2  = (const float*)d_in[5];
    const float* W2r = (const float*)d_in[6];
    const int* edge_index = (const int*)d_in[7];
    const int* pred_edges = (const int*)d_in[8];
    float* out = (float*)d_out;

    const int* src = edge_index;
    const int* dst = edge_index + EE;
    const int* ps = pred_edges;
    const int* pd = pred_edges + EPP;

    static int attr_done = 0;
    if (!attr_done) {
        cudaFuncSetAttribute(k_mm, cudaFuncAttributeMaxDynamicSharedMemorySize, SMEM_MM);
        attr_done = 1;
    }

    k_zero_deg<<<(NN + 255) / 256, 256>>>();
    k_count<<<(EE / 4 + 255) / 256, 256>>>(dst);
    k_scan<<<1, 1024>>>();
    k_fill<<<(EE / 4 + 255) / 256, 256>>>(src, dst);
    k_prepackW<<<(2 * DIM * KK + 255) / 256, 256>>>(W1l, W1r, W2l, W2r);

    k_agg<<<(NN * 32 + 255) / 256, 256>>>(x, 0);
    k_mm<<<MTILES, 256, SMEM_MM>>>(b1, 1);
    k_agg<<<(NN * 32 + 255) / 256, 256>>>(nullptr, 1);
    k_mm<<<MTILES, 256, SMEM_MM>>>(b2, 2);
    k_pred<<<(EPP * 32 + 255) / 256, 256>>>(ps, pd, out);
}

// round 9
// speedup vs baseline: 1.7124x; 1.7124x over previous
#include <cuda_runtime.h>
#include <cuda_bf16.h>
#include <cstdint>

#define NN 50000
#define EE 800000
#define EPP 200000
#define DIM 128
#define KK 256
#define MTILES ((NN + 127) / 128)
#define NBLK 49  // ceil(NN/1024)

// ---------------- scratch ----------------------------------------------------
__device__ int   g_deg[NN];
__device__ int   g_rowptr[NN + 1];
__device__ int   g_cursor[NN];
__device__ int   g_csr_src[EE];
__device__ int   g_bsum[NBLK];
__device__ int   g_boff[NBLK];
__device__ float g_h[NN * DIM];
__device__ float g_z[NN * DIM];
__device__ __nv_bfloat16 g_Ahi[NN * KK];      // [node][k]  k<128: agg, k>=128: feat
__device__ __nv_bfloat16 g_Alo[NN * KK];
__device__ __nv_bfloat16 g_Whi[2 * DIM * KK]; // [layer][n][k]
__device__ __nv_bfloat16 g_Wlo[2 * DIM * KK];

__device__ __forceinline__ uint32_t smem_u32(const void* p) {
    uint32_t a;
    asm("{ .reg .u64 t; cvta.to.shared.u64 t, %1; cvt.u32.u64 %0, t; }" : "=r"(a) : "l"(p));
    return a;
}

__device__ __forceinline__ void split_store4(float4 v, __nv_bfloat16* hp, __nv_bfloat16* lp) {
    __nv_bfloat162 h0 = __floats2bfloat162_rn(v.x, v.y);
    __nv_bfloat162 h1 = __floats2bfloat162_rn(v.z, v.w);
    float lx = v.x - __bfloat162float(h0.x);
    float ly = v.y - __bfloat162float(h0.y);
    float lz = v.z - __bfloat162float(h1.x);
    float lw = v.w - __bfloat162float(h1.y);
    __nv_bfloat162 l0 = __floats2bfloat162_rn(lx, ly);
    __nv_bfloat162 l1 = __floats2bfloat162_rn(lz, lw);
    *(uint2*)hp = make_uint2(*(unsigned*)&h0, *(unsigned*)&h1);
    *(uint2*)lp = make_uint2(*(unsigned*)&l0, *(unsigned*)&l1);
}
__device__ __forceinline__ void split_store2(float a, float b, __nv_bfloat16* hp, __nv_bfloat16* lp) {
    __nv_bfloat162 h = __floats2bfloat162_rn(a, b);
    float la = a - __bfloat162float(h.x);
    float lb = b - __bfloat162float(h.y);
    __nv_bfloat162 l = __floats2bfloat162_rn(la, lb);
    *(unsigned*)hp = *(unsigned*)&h;
    *(unsigned*)lp = *(unsigned*)&l;
}

// ---------------- init: zero deg + weight prepack (merged) -------------------
__global__ void k_init(const float* __restrict__ W1l, const float* __restrict__ W1r,
                       const float* __restrict__ W2l, const float* __restrict__ W2r) {
    int i = blockIdx.x * blockDim.x + threadIdx.x;
    if (i < NN) g_deg[i] = 0;
    int idx = i - NN;
    if (idx >= 0 && idx < 2 * DIM * KK) {
        int l = idx / (DIM * KK);
        int rem = idx - l * (DIM * KK);
        int n = rem / KK, k = rem % KK;
        const float* Wl = l ? W2l : W1l;
        const float* Wr = l ? W2r : W1r;
        float w = (k < DIM) ? Wl[k * DIM + n] : Wr[(k - DIM) * DIM + n];
        __nv_bfloat16 hi = __float2bfloat16(w);
        __nv_bfloat16 lo = __float2bfloat16(w - __bfloat162float(hi));
        g_Whi[idx] = hi;
        g_Wlo[idx] = lo;
    }
}

// ---------------- CSR build --------------------------------------------------
__global__ void k_count(const int* __restrict__ dst) {
    int q = blockIdx.x * blockDim.x + threadIdx.x;
    if (q >= EE / 4) return;
    int4 d4 = ((const int4*)dst)[q];
    unsigned d0 = (unsigned)d4.x, d1 = (unsigned)d4.y,
             d2 = (unsigned)d4.z, d3 = (unsigned)d4.w;
    if (d0 < NN) atomicAdd(&g_deg[d0], 1);
    if (d1 < NN) atomicAdd(&g_deg[d1], 1);
    if (d2 < NN) atomicAdd(&g_deg[d2], 1);
    if (d3 < NN) atomicAdd(&g_deg[d3], 1);
}

// phase 1: per-block inclusive scan of 1024 elems; local result -> rowptr[i+1]
__global__ void k_scan1() {
    __shared__ int warp_sums[32];
    int tid = threadIdx.x;
    int i = blockIdx.x * 1024 + tid;
    int v = (i < NN) ? g_deg[i] : 0;
    int x = v;
    #pragma unroll
    for (int o = 1; o < 32; o <<= 1) {
        int y = __shfl_up_sync(0xffffffffu, x, o);
        if ((tid & 31) >= o) x += y;
    }
    if ((tid & 31) == 31) warp_sums[tid >> 5] = x;
    __syncthreads();
    if (tid < 32) {
        int w = warp_sums[tid];
        #pragma unroll
        for (int o = 1; o < 32; o <<= 1) {
            int y = __shfl_up_sync(0xffffffffu, w, o);
            if (tid >= o) w += y;
        }
        warp_sums[tid] = w;
    }
    __syncthreads();
    int incl = x + ((tid >= 32) ? warp_sums[(tid >> 5) - 1] : 0);
    if (i < NN) g_rowptr[i + 1] = incl;
    if (tid == 1023) g_bsum[blockIdx.x] = incl;
}
// phase 2: scan 49 block sums (1 block, 64 threads)
__global__ void k_scan2() {
    __shared__ int s[64];
    int tid = threadIdx.x;
    int v = (tid < NBLK) ? g_bsum[tid] : 0;
    s[tid] = v;
    __syncthreads();
    #pragma unroll
    for (int o = 1; o < 64; o <<= 1) {
        int y = (tid >= o) ? s[tid - o] : 0;
        __syncthreads();
        s[tid] += y;
        __syncthreads();
    }
    if (tid < NBLK) g_boff[tid] = s[tid] - v;  // exclusive
}
// phase 3: add offsets, write cursor, rowptr[0]
__global__ void k_scan3() {
    int i = blockIdx.x * blockDim.x + threadIdx.x;
    if (i >= NN) return;
    int incl = g_rowptr[i + 1] + g_boff[i >> 10];
    g_rowptr[i + 1] = incl;
    g_cursor[i] = incl - g_deg[i];
    if (i == 0) g_rowptr[0] = 0;
}

__global__ void k_fill(const int* __restrict__ src, const int* __restrict__ dst) {
    int q = blockIdx.x * blockDim.x + threadIdx.x;
    if (q >= EE / 4) return;
    int4 d4 = ((const int4*)dst)[q];
    int4 s4 = ((const int4*)src)[q];
    #pragma unroll
    for (int j = 0; j < 4; ++j) {
        unsigned d = (unsigned)(&d4.x)[j];
        unsigned s = (unsigned)(&s4.x)[j];
        if (d < NN && s < NN) {
            int p = atomicAdd(&g_cursor[d], 1);
            if ((unsigned)p < EE) g_csr_src[p] = (int)s;
        }
    }
}

// ---------------- mean aggregation (warp per node) ---------------------------
__global__ void k_agg(const float* __restrict__ feat_in, int use_h) {
    const float* feat = use_h ? g_h : feat_in;
    int warp_id = (blockIdx.x * blockDim.x + threadIdx.x) >> 5;
    int lane = threadIdx.x & 31;
    if (warp_id >= NN) return;
    int n = warp_id;
    int start = g_rowptr[n], end = g_rowptr[n + 1];
    const float4* f4 = (const float4*)feat;
    float4 a0 = make_float4(0.f, 0.f, 0.f, 0.f);
    float4 a1 = a0, a2 = a0, a3 = a0;
    for (int base = start; base < end; base += 32) {
        int m = min(32, end - base);
        int sid = (lane < m) ? g_csr_src[base + lane] : 0;
        int t = 0;
        for (; t + 4 <= m; t += 4) {
            int s0 = __shfl_sync(0xffffffffu, sid, t);
            int s1 = __shfl_sync(0xffffffffu, sid, t + 1);
            int s2 = __shfl_sync(0xffffffffu, sid, t + 2);
            int s3 = __shfl_sync(0xffffffffu, sid, t + 3);
            float4 v0 = f4[(size_t)s0 * 32 + lane];
            float4 v1 = f4[(size_t)s1 * 32 + lane];
            float4 v2 = f4[(size_t)s2 * 32 + lane];
            float4 v3 = f4[(size_t)s3 * 32 + lane];
            a0.x += v0.x; a0.y += v0.y; a0.z += v0.z; a0.w += v0.w;
            a1.x += v1.x; a1.y += v1.y; a1.z += v1.z; a1.w += v1.w;
            a2.x += v2.x; a2.y += v2.y; a2.z += v2.z; a2.w += v2.w;
            a3.x += v3.x; a3.y += v3.y; a3.z += v3.z; a3.w += v3.w;
        }
        for (; t < m; ++t) {
            int s = __shfl_sync(0xffffffffu, sid, t);
            float4 v = f4[(size_t)s * 32 + lane];
            a0.x += v.x; a0.y += v.y; a0.z += v.z; a0.w += v.w;
        }
    }
    a0.x += a1.x + a2.x + a3.x;
    a0.y += a1.y + a2.y + a3.y;
    a0.z += a1.z + a2.z + a3.z;
    a0.w += a1.w + a2.w + a3.w;
    int d = end - start;
    float inv = 1.0f / (float)max(d, 1);
    a0.x *= inv; a0.y *= inv; a0.z *= inv; a0.w *= inv;
    size_t off = (size_t)n * KK + lane * 4;
    split_store4(a0, &g_Ahi[off], &g_Alo[off]);
    if (!use_h) {
        float4 v = f4[(size_t)n * 32 + lane];
        size_t o2 = (size_t)n * KK + DIM + lane * 4;
        split_store4(v, &g_Ahi[o2], &g_Alo[o2]);
    }
}

// ---------------- bf16-split GEMM: cp.async double-buffered ------------------
// K chunks of 32; 4 tiles/chunk [128 rows x 32 bf16], row stride 80B (no swizzle,
// r*20 mod 32 covers 8 distinct bank groups -> ldmatrix conflict-free).
#define CH 32
#define TSTRIDE 80
#define TILE_B (128 * TSTRIDE)  // 10240
#define BUF_B (4 * TILE_B)      // 40960
#define SMEM_MM (2 * BUF_B)     // 81920
#define NCHUNK (KK / CH)        // 8

__device__ __forceinline__ void ldsm_x4(uint32_t r[4], uint32_t saddr) {
    asm volatile("ldmatrix.sync.aligned.m8n8.x4.shared.b16 {%0,%1,%2,%3}, [%4];"
                 : "=r"(r[0]), "=r"(r[1]), "=r"(r[2]), "=r"(r[3]) : "r"(saddr));
}
__device__ __forceinline__ void cp16(uint32_t dst, const void* src, bool pred) {
    int sz = pred ? 16 : 0;
    asm volatile("cp.async.cg.shared.global [%0], [%1], 16, %2;"
                 :: "r"(dst), "l"(src), "r"(sz));
}
#define CP_COMMIT() asm volatile("cp.async.commit_group;" ::: "memory")
#define CP_WAIT1() asm volatile("cp.async.wait_group 1;" ::: "memory")
#define CP_WAIT0() asm volatile("cp.async.wait_group 0;" ::: "memory")

#define MMA_BF16(d, a, b0, b1)                                                    \
    asm volatile("mma.sync.aligned.m16n8k16.row.col.f32.bf16.bf16.f32 "           \
                 "{%0,%1,%2,%3}, {%4,%5,%6,%7}, {%8,%9}, {%0,%1,%2,%3};"          \
                 : "+f"((d)[0]), "+f"((d)[1]), "+f"((d)[2]), "+f"((d)[3])         \
                 : "r"((a)[0]), "r"((a)[1]), "r"((a)[2]), "r"((a)[3]),            \
                   "r"(b0), "r"(b1))

__global__ void __launch_bounds__(256) k_mm(const float* __restrict__ bias, int layer) {
    extern __shared__ char smem[];
    uint32_t sb = smem_u32(smem);
    int tid = threadIdx.x, w = tid >> 5, l = tid & 31;
    int row0 = blockIdx.x * 128;
    const __nv_bfloat16* Wh = g_Whi + (layer - 1) * DIM * KK;
    const __nv_bfloat16* Wl = g_Wlo + (layer - 1) * DIM * KK;

    float acc[16][4];
    #pragma unroll
    for (int i = 0; i < 16; ++i)
        acc[i][0] = acc[i][1] = acc[i][2] = acc[i][3] = 0.f;

    int rA = w * 16 + (l & 7) + ((l >> 3) & 1) * 8;
    int uA_lane = (l >> 4) & 1;
    int rB_lane = (l & 7) + ((l >> 4) & 1) * 8;
    int uB_lane = (l >> 3) & 1;

    // load chunk c into buffer buf
    auto load_chunk = [&](int c, int buf) {
        #pragma unroll
        for (int it = 0; it < 8; ++it) {
            int i = tid + it * 256;           // 0..2047
            int t = i >> 9, s = i & 511;
            int r = s >> 2, u4 = s & 3;
            uint32_t dst = sb + buf * BUF_B + t * TILE_B + r * TSTRIDE + u4 * 16;
            const __nv_bfloat16* p;
            bool ok = true;
            if (t < 2) {
                int gr = row0 + r;
                ok = gr < NN;
                p = (t == 0 ? g_Ahi : g_Alo) + (size_t)(ok ? gr : 0) * KK + c * CH + u4 * 8;
            } else {
                p = (t == 2 ? Wh : Wl) + (size_t)r * KK + c * CH + u4 * 8;
            }
            cp16(dst, p, ok);
        }
        CP_COMMIT();
    };

    load_chunk(0, 0);
    for (int c = 0; c < NCHUNK; ++c) {
        int b = c & 1;
        if (c + 1 < NCHUNK) {
            load_chunk(c + 1, 1 - b);
            CP_WAIT1();
        } else {
            CP_WAIT0();
        }
        __syncthreads();
        uint32_t base = sb + b * BUF_B;
        #pragma unroll
        for (int ks = 0; ks < 2; ++ks) {
            int uA = ks * 2 + uA_lane;
            uint32_t ah[4], al[4];
            ldsm_x4(ah, base + (uint32_t)(rA * TSTRIDE + uA * 16));
            ldsm_x4(al, base + TILE_B + (uint32_t)(rA * TSTRIDE + uA * 16));
            int uB = ks * 2 + uB_lane;
            #pragma unroll
            for (int p = 0; p < 8; ++p) {
                int rB = p * 16 + rB_lane;
                uint32_t off = (uint32_t)(rB * TSTRIDE + uB * 16);
                uint32_t bh[4], bl[4];
                ldsm_x4(bh, base + 2 * TILE_B + off);
                ldsm_x4(bl, base + 3 * TILE_B + off);
                MMA_BF16(acc[2 * p], ah, bh[0], bh[1]);
                MMA_BF16(acc[2 * p], al, bh[0], bh[1]);
                MMA_BF16(acc[2 * p], ah, bl[0], bl[1]);
                MMA_BF16(acc[2 * p + 1], ah, bh[2], bh[3]);
                MMA_BF16(acc[2 * p + 1], al, bh[2], bh[3]);
                MMA_BF16(acc[2 * p + 1], ah, bl[2], bl[3]);
            }
        }
        __syncthreads();
    }

    float* outp = (layer == 1) ? g_h : g_z;
    int r1 = row0 + w * 16 + (l >> 2);
    int r2 = r1 + 8;
    #pragma unroll
    for (int nt = 0; nt < 16; ++nt) {
        int c = nt * 8 + (l & 3) * 2;
        float2 b2 = *(const float2*)&bias[c];
        float* d = acc[nt];
        float v0 = d[0] + b2.x, v1 = d[1] + b2.y;
        float v2 = d[2] + b2.x, v3 = d[3] + b2.y;
        if (layer == 1) {
            v0 = fmaxf(v0, 0.f); v1 = fmaxf(v1, 0.f);
            v2 = fmaxf(v2, 0.f); v3 = fmaxf(v3, 0.f);
        }
        if (r1 < NN) {
            *(float2*)&outp[(size_t)r1 * DIM + c] = make_float2(v0, v1);
            if (layer == 1) {
                size_t o = (size_t)r1 * KK + DIM + c;
                split_store2(v0, v1, &g_Ahi[o], &g_Alo[o]);
            }
        }
        if (r2 < NN) {
            *(float2*)&outp[(size_t)r2 * DIM + c] = make_float2(v2, v3);
            if (layer == 1) {
                size_t o = (size_t)r2 * KK + DIM + c;
                split_store2(v2, v3, &g_Ahi[o], &g_Alo[o]);
            }
        }
    }
}

// ---------------- link prediction (warp per 4 pred edges) --------------------
__global__ void k_pred(const int* __restrict__ ps, const int* __restrict__ pd,
                       float* __restrict__ out) {
    int warp_id = (blockIdx.x * blockDim.x + threadIdx.x) >> 5;
    int lane = threadIdx.x & 31;
    int e0 = warp_id * 4;
    if (e0 >= EPP) return;
    const float4* z4 = (const float4*)g_z;
    float dres[4];
    #pragma unroll
    for (int j = 0; j < 4; ++j) {
        unsigned a = (unsigned)ps[e0 + j], b = (unsigned)pd[e0 + j];
        if (a >= NN) a = 0;
        if (b >= NN) b = 0;
        float4 u = z4[(size_t)a * 32 + lane];
        float4 v = z4[(size_t)b * 32 + lane];
        dres[j] = u.x * v.x + u.y * v.y + u.z * v.z + u.w * v.w;
    }
    #pragma unroll
    for (int j = 0; j < 4; ++j) {
        float d = dres[j];
        #pragma unroll
        for (int o = 16; o > 0; o >>= 1) d += __shfl_xor_sync(0xffffffffu, d, o);
        if (lane == 0) out[e0 + j] = d;
    }
}

// ---------------- launch -----------------------------------------------------
extern "C" void kernel_launch(void* const* d_in, const int* in_sizes, int n_in,
                              void* d_out, int out_size) {
    const float* x   = (const float*)d_in[0];
    const float* W1l = (const float*)d_in[1];
    const float* b1  = (const float*)d_in[2];
    const float* W1r = (const float*)d_in[3];
    const float* W2l = (const float*)d_in[4];
    const float* b2  = (const float*)d_in[5];
    const float* W2r = (const float*)d_in[6];
    const int* edge_index = (const int*)d_in[7];
    const int* pred_edges = (const int*)d_in[8];
    float* out = (float*)d_out;

    const int* src = edge_index;
    const int* dst = edge_index + EE;
    const int* ps = pred_edges;
    const int* pd = pred_edges + EPP;

    static int attr_done = 0;
    if (!attr_done) {
        cudaFuncSetAttribute(k_mm, cudaFuncAttributeMaxDynamicSharedMemorySize, SMEM_MM);
        attr_done = 1;
    }

    k_init<<<(NN + 2 * DIM * KK + 255) / 256, 256>>>(W1l, W1r, W2l, W2r);
    k_count<<<(EE / 4 + 255) / 256, 256>>>(dst);
    k_scan1<<<NBLK, 1024>>>();
    k_scan2<<<1, 64>>>();
    k_scan3<<<(NN + 255) / 256, 256>>>();
    k_fill<<<(EE / 4 + 255) / 256, 256>>>(src, dst);

    k_agg<<<(NN * 32 + 255) / 256, 256>>>(x, 0);
    k_mm<<<MTILES, 256, SMEM_MM>>>(b1, 1);
    k_agg<<<(NN * 32 + 255) / 256, 256>>>(nullptr, 1);
    k_mm<<<MTILES, 256, SMEM_MM>>>(b2, 2);
    k_pred<<<(EPP / 4 * 32 + 255) / 256, 256>>>(ps, pd, out);
}

// round 11
// speedup vs baseline: 1.7591x; 1.0273x over previous
#include <cuda_runtime.h>
#include <cuda_bf16.h>
#include <cstdint>

#define NN 50000
#define EE 800000
#define EPP 200000
#define DIM 128
#define KK 256
#define MTILES ((NN + 127) / 128)
#define NBLK 49  // ceil(NN/1024)

// ---------------- scratch ----------------------------------------------------
__device__ int   g_deg[NN];
__device__ int   g_rowptr[NN + 1];
__device__ int   g_cursor[NN];
__device__ int   g_csr_src[EE];
__device__ int   g_bsum[NBLK];
__device__ int   g_boff[NBLK];
__device__ float g_h[NN * DIM];
__device__ float g_z[NN * DIM];
__device__ __nv_bfloat16 g_Ahi[NN * KK];      // [node][k]  k<128: agg, k>=128: feat
__device__ __nv_bfloat16 g_Alo[NN * KK];
__device__ __nv_bfloat16 g_Whi[2 * DIM * KK]; // [layer][n][k]
__device__ __nv_bfloat16 g_Wlo[2 * DIM * KK];

__device__ __forceinline__ uint32_t smem_u32(const void* p) {
    uint32_t a;
    asm("{ .reg .u64 t; cvta.to.shared.u64 t, %1; cvt.u32.u64 %0, t; }" : "=r"(a) : "l"(p));
    return a;
}

__device__ __forceinline__ void split_store4(float4 v, __nv_bfloat16* hp, __nv_bfloat16* lp) {
    __nv_bfloat162 h0 = __floats2bfloat162_rn(v.x, v.y);
    __nv_bfloat162 h1 = __floats2bfloat162_rn(v.z, v.w);
    float lx = v.x - __bfloat162float(h0.x);
    float ly = v.y - __bfloat162float(h0.y);
    float lz = v.z - __bfloat162float(h1.x);
    float lw = v.w - __bfloat162float(h1.y);
    __nv_bfloat162 l0 = __floats2bfloat162_rn(lx, ly);
    __nv_bfloat162 l1 = __floats2bfloat162_rn(lz, lw);
    *(uint2*)hp = make_uint2(*(unsigned*)&h0, *(unsigned*)&h1);
    *(uint2*)lp = make_uint2(*(unsigned*)&l0, *(unsigned*)&l1);
}
__device__ __forceinline__ void split_store2(float a, float b, __nv_bfloat16* hp, __nv_bfloat16* lp) {
    __nv_bfloat162 h = __floats2bfloat162_rn(a, b);
    float la = a - __bfloat162float(h.x);
    float lb = b - __bfloat162float(h.y);
    __nv_bfloat162 l = __floats2bfloat162_rn(la, lb);
    *(unsigned*)hp = *(unsigned*)&h;
    *(unsigned*)lp = *(unsigned*)&l;
}

// ---------------- init: zero deg + weight prepack (merged) -------------------
__global__ void k_init(const float* __restrict__ W1l, const float* __restrict__ W1r,
                       const float* __restrict__ W2l, const float* __restrict__ W2r) {
    int i = blockIdx.x * blockDim.x + threadIdx.x;
    if (i < NN) g_deg[i] = 0;
    int idx = i - NN;
    if (idx >= 0 && idx < 2 * DIM * KK) {
        int l = idx / (DIM * KK);
        int rem = idx - l * (DIM * KK);
        int n = rem / KK, k = rem % KK;
        const float* Wl = l ? W2l : W1l;
        const float* Wr = l ? W2r : W1r;
        float w = (k < DIM) ? Wl[k * DIM + n] : Wr[(k - DIM) * DIM + n];
        __nv_bfloat16 hi = __float2bfloat16(w);
        __nv_bfloat16 lo = __float2bfloat16(w - __bfloat162float(hi));
        g_Whi[idx] = hi;
        g_Wlo[idx] = lo;
    }
}

// ---------------- CSR build --------------------------------------------------
__global__ void k_count(const int* __restrict__ dst) {
    int q = blockIdx.x * blockDim.x + threadIdx.x;
    if (q >= EE / 4) return;
    int4 d4 = ((const int4*)dst)[q];
    unsigned d0 = (unsigned)d4.x, d1 = (unsigned)d4.y,
             d2 = (unsigned)d4.z, d3 = (unsigned)d4.w;
    if (d0 < NN) atomicAdd(&g_deg[d0], 1);
    if (d1 < NN) atomicAdd(&g_deg[d1], 1);
    if (d2 < NN) atomicAdd(&g_deg[d2], 1);
    if (d3 < NN) atomicAdd(&g_deg[d3], 1);
}

// phase 1: per-block inclusive scan of 1024 elems; local result -> rowptr[i+1]
__global__ void k_scan1() {
    __shared__ int warp_sums[32];
    int tid = threadIdx.x;
    int i = blockIdx.x * 1024 + tid;
    int v = (i < NN) ? g_deg[i] : 0;
    int x = v;
    #pragma unroll
    for (int o = 1; o < 32; o <<= 1) {
        int y = __shfl_up_sync(0xffffffffu, x, o);
        if ((tid & 31) >= o) x += y;
    }
    if ((tid & 31) == 31) warp_sums[tid >> 5] = x;
    __syncthreads();
    if (tid < 32) {
        int w = warp_sums[tid];
        #pragma unroll
        for (int o = 1; o < 32; o <<= 1) {
            int y = __shfl_up_sync(0xffffffffu, w, o);
            if (tid >= o) w += y;
        }
        warp_sums[tid] = w;
    }
    __syncthreads();
    int incl = x + ((tid >= 32) ? warp_sums[(tid >> 5) - 1] : 0);
    if (i < NN) g_rowptr[i + 1] = incl;
    if (tid == 1023) g_bsum[blockIdx.x] = incl;
}
// phase 2: scan 49 block sums (1 block, 64 threads)
__global__ void k_scan2() {
    __shared__ int s[64];
    int tid = threadIdx.x;
    int v = (tid < NBLK) ? g_bsum[tid] : 0;
    s[tid] = v;
    __syncthreads();
    #pragma unroll
    for (int o = 1; o < 64; o <<= 1) {
        int y = (tid >= o) ? s[tid - o] : 0;
        __syncthreads();
        s[tid] += y;
        __syncthreads();
    }
    if (tid < NBLK) g_boff[tid] = s[tid] - v;  // exclusive
}
// phase 3: add offsets, write cursor, rowptr[0]
__global__ void k_scan3() {
    int i = blockIdx.x * blockDim.x + threadIdx.x;
    if (i >= NN) return;
    int incl = g_rowptr[i + 1] + g_boff[i >> 10];
    g_rowptr[i + 1] = incl;
    g_cursor[i] = incl - g_deg[i];
    if (i == 0) g_rowptr[0] = 0;
}

__global__ void k_fill(const int* __restrict__ src, const int* __restrict__ dst) {
    int q = blockIdx.x * blockDim.x + threadIdx.x;
    if (q >= EE / 4) return;
    int4 d4 = ((const int4*)dst)[q];
    int4 s4 = ((const int4*)src)[q];
    #pragma unroll
    for (int j = 0; j < 4; ++j) {
        unsigned d = (unsigned)(&d4.x)[j];
        unsigned s = (unsigned)(&s4.x)[j];
        if (d < NN && s < NN) {
            int p = atomicAdd(&g_cursor[d], 1);
            if ((unsigned)p < EE) g_csr_src[p] = (int)s;
        }
    }
}

// ---------------- mean aggregation (warp per node) ---------------------------
__global__ void k_agg(const float* __restrict__ feat_in, int use_h) {
    const float* feat = use_h ? g_h : feat_in;
    int warp_id = (blockIdx.x * blockDim.x + threadIdx.x) >> 5;
    int lane = threadIdx.x & 31;
    if (warp_id >= NN) return;
    int n = warp_id;
    int start = g_rowptr[n], end = g_rowptr[n + 1];
    const float4* f4 = (const float4*)feat;
    float4 a0 = make_float4(0.f, 0.f, 0.f, 0.f);
    float4 a1 = a0, a2 = a0, a3 = a0;
    for (int base = start; base < end; base += 32) {
        int m = min(32, end - base);
        int sid = (lane < m) ? g_csr_src[base + lane] : 0;
        int t = 0;
        for (; t + 4 <= m; t += 4) {
            int s0 = __shfl_sync(0xffffffffu, sid, t);
            int s1 = __shfl_sync(0xffffffffu, sid, t + 1);
            int s2 = __shfl_sync(0xffffffffu, sid, t + 2);
            int s3 = __shfl_sync(0xffffffffu, sid, t + 3);
            float4 v0 = f4[(size_t)s0 * 32 + lane];
            float4 v1 = f4[(size_t)s1 * 32 + lane];
            float4 v2 = f4[(size_t)s2 * 32 + lane];
            float4 v3 = f4[(size_t)s3 * 32 + lane];
            a0.x += v0.x; a0.y += v0.y; a0.z += v0.z; a0.w += v0.w;
            a1.x += v1.x; a1.y += v1.y; a1.z += v1.z; a1.w += v1.w;
            a2.x += v2.x; a2.y += v2.y; a2.z += v2.z; a2.w += v2.w;
            a3.x += v3.x; a3.y += v3.y; a3.z += v3.z; a3.w += v3.w;
        }
        for (; t < m; ++t) {
            int s = __shfl_sync(0xffffffffu, sid, t);
            float4 v = f4[(size_t)s * 32 + lane];
            a0.x += v.x; a0.y += v.y; a0.z += v.z; a0.w += v.w;
        }
    }
    a0.x += a1.x + a2.x + a3.x;
    a0.y += a1.y + a2.y + a3.y;
    a0.z += a1.z + a2.z + a3.z;
    a0.w += a1.w + a2.w + a3.w;
    int d = end - start;
    float inv = 1.0f / (float)max(d, 1);
    a0.x *= inv; a0.y *= inv; a0.z *= inv; a0.w *= inv;
    size_t off = (size_t)n * KK + lane * 4;
    split_store4(a0, &g_Ahi[off], &g_Alo[off]);
    if (!use_h) {
        float4 v = f4[(size_t)n * 32 + lane];
        size_t o2 = (size_t)n * KK + DIM + lane * 4;
        split_store4(v, &g_Ahi[o2], &g_Alo[o2]);
    }
}

// ---------------- bf16-split GEMM: cp.async double-buffered ------------------
// K chunks of 32; 4 tiles/chunk [128 rows x 32 bf16], row stride 80B (no swizzle,
// r*20 mod 32 covers 8 distinct bank groups -> ldmatrix conflict-free).
#define CH 32
#define TSTRIDE 80
#define TILE_B (128 * TSTRIDE)  // 10240
#define BUF_B (4 * TILE_B)      // 40960
#define SMEM_MM (2 * BUF_B)     // 81920
#define NCHUNK (KK / CH)        // 8

__device__ __forceinline__ void ldsm_x4(uint32_t r[4], uint32_t saddr) {
    asm volatile("ldmatrix.sync.aligned.m8n8.x4.shared.b16 {%0,%1,%2,%3}, [%4];"
                 : "=r"(r[0]), "=r"(r[1]), "=r"(r[2]), "=r"(r[3]) : "r"(saddr));
}
__device__ __forceinline__ void cp16(uint32_t dst, const void* src, bool pred) {
    int sz = pred ? 16 : 0;
    asm volatile("cp.async.cg.shared.global [%0], [%1], 16, %2;"
                 :: "r"(dst), "l"(src), "r"(sz));
}
#define CP_COMMIT() asm volatile("cp.async.commit_group;" ::: "memory")
#define CP_WAIT1() asm volatile("cp.async.wait_group 1;" ::: "memory")
#define CP_WAIT0() asm volatile("cp.async.wait_group 0;" ::: "memory")

#define MMA_BF16(d, a, b0, b1)                                                    \
    asm volatile("mma.sync.aligned.m16n8k16.row.col.f32.bf16.bf16.f32 "           \
                 "{%0,%1,%2,%3}, {%4,%5,%6,%7}, {%8,%9}, {%0,%1,%2,%3};"          \
                 : "+f"((d)[0]), "+f"((d)[1]), "+f"((d)[2]), "+f"((d)[3])         \
                 : "r"((a)[0]), "r"((a)[1]), "r"((a)[2]), "r"((a)[3]),            \
                   "r"(b0), "r"(b1))

__global__ void __launch_bounds__(256) k_mm(const float* __restrict__ bias, int layer) {
    extern __shared__ char smem[];
    uint32_t sb = smem_u32(smem);
    int tid = threadIdx.x, w = tid >> 5, l = tid & 31;
    int row0 = blockIdx.x * 128;
    const __nv_bfloat16* Wh = g_Whi + (layer - 1) * DIM * KK;
    const __nv_bfloat16* Wl = g_Wlo + (layer - 1) * DIM * KK;

    float acc[16][4];
    #pragma unroll
    for (int i = 0; i < 16; ++i)
        acc[i][0] = acc[i][1] = acc[i][2] = acc[i][3] = 0.f;

    int rA = w * 16 + (l & 7) + ((l >> 3) & 1) * 8;
    int uA_lane = (l >> 4) & 1;
    int rB_lane = (l & 7) + ((l >> 4) & 1) * 8;
    int uB_lane = (l >> 3) & 1;

    // load chunk c into buffer buf
    auto load_chunk = [&](int c, int buf) {
        #pragma unroll
        for (int it = 0; it < 8; ++it) {
            int i = tid + it * 256;           // 0..2047
            int t = i >> 9, s = i & 511;
            int r = s >> 2, u4 = s & 3;
            uint32_t dst = sb + buf * BUF_B + t * TILE_B + r * TSTRIDE + u4 * 16;
            const __nv_bfloat16* p;
            bool ok = true;
            if (t < 2) {
                int gr = row0 + r;
                ok = gr < NN;
                p = (t == 0 ? g_Ahi : g_Alo) + (size_t)(ok ? gr : 0) * KK + c * CH + u4 * 8;
            } else {
                p = (t == 2 ? Wh : Wl) + (size_t)r * KK + c * CH + u4 * 8;
            }
            cp16(dst, p, ok);
        }
        CP_COMMIT();
    };

    load_chunk(0, 0);
    for (int c = 0; c < NCHUNK; ++c) {
        int b = c & 1;
        if (c + 1 < NCHUNK) {
            load_chunk(c + 1, 1 - b);
            CP_WAIT1();
        } else {
            CP_WAIT0();
        }
        __syncthreads();
        uint32_t base = sb + b * BUF_B;
        #pragma unroll
        for (int ks = 0; ks < 2; ++ks) {
            int uA = ks * 2 + uA_lane;
            uint32_t ah[4], al[4];
            ldsm_x4(ah, base + (uint32_t)(rA * TSTRIDE + uA * 16));
            ldsm_x4(al, base + TILE_B + (uint32_t)(rA * TSTRIDE + uA * 16));
            int uB = ks * 2 + uB_lane;
            #pragma unroll
            for (int p = 0; p < 8; ++p) {
                int rB = p * 16 + rB_lane;
                uint32_t off = (uint32_t)(rB * TSTRIDE + uB * 16);
                uint32_t bh[4], bl[4];
                ldsm_x4(bh, base + 2 * TILE_B + off);
                ldsm_x4(bl, base + 3 * TILE_B + off);
                MMA_BF16(acc[2 * p], ah, bh[0], bh[1]);
                MMA_BF16(acc[2 * p], al, bh[0], bh[1]);
                MMA_BF16(acc[2 * p], ah, bl[0], bl[1]);
                MMA_BF16(acc[2 * p + 1], ah, bh[2], bh[3]);
                MMA_BF16(acc[2 * p + 1], al, bh[2], bh[3]);
                MMA_BF16(acc[2 * p + 1], ah, bl[2], bl[3]);
            }
        }
        __syncthreads();
    }

    float* outp = (layer == 1) ? g_h : g_z;
    int r1 = row0 + w * 16 + (l >> 2);
    int r2 = r1 + 8;
    #pragma unroll
    for (int nt = 0; nt < 16; ++nt) {
        int c = nt * 8 + (l & 3) * 2;
        float2 b2 = *(const float2*)&bias[c];
        float* d = acc[nt];
        float v0 = d[0] + b2.x, v1 = d[1] + b2.y;
        float v2 = d[2] + b2.x, v3 = d[3] + b2.y;
        if (layer == 1) {
            v0 = fmaxf(v0, 0.f); v1 = fmaxf(v1, 0.f);
            v2 = fmaxf(v2, 0.f); v3 = fmaxf(v3, 0.f);
        }
        if (r1 < NN) {
            *(float2*)&outp[(size_t)r1 * DIM + c] = make_float2(v0, v1);
            if (layer == 1) {
                size_t o = (size_t)r1 * KK + DIM + c;
                split_store2(v0, v1, &g_Ahi[o], &g_Alo[o]);
            }
        }
        if (r2 < NN) {
            *(float2*)&outp[(size_t)r2 * DIM + c] = make_float2(v2, v3);
            if (layer == 1) {
                size_t o = (size_t)r2 * KK + DIM + c;
                split_store2(v2, v3, &g_Ahi[o], &g_Alo[o]);
            }
        }
    }
}

// ---------------- link prediction (warp per 4 pred edges) --------------------
__global__ void k_pred(const int* __restrict__ ps, const int* __restrict__ pd,
                       float* __restrict__ out) {
    int warp_id = (blockIdx.x * blockDim.x + threadIdx.x) >> 5;
    int lane = threadIdx.x & 31;
    int e0 = warp_id * 4;
    if (e0 >= EPP) return;
    const float4* z4 = (const float4*)g_z;
    float dres[4];
    #pragma unroll
    for (int j = 0; j < 4; ++j) {
        unsigned a = (unsigned)ps[e0 + j], b = (unsigned)pd[e0 + j];
        if (a >= NN) a = 0;
        if (b >= NN) b = 0;
        float4 u = z4[(size_t)a * 32 + lane];
        float4 v = z4[(size_t)b * 32 + lane];
        dres[j] = u.x * v.x + u.y * v.y + u.z * v.z + u.w * v.w;
    }
    #pragma unroll
    for (int j = 0; j < 4; ++j) {
        float d = dres[j];
        #pragma unroll
        for (int o = 16; o > 0; o >>= 1) d += __shfl_xor_sync(0xffffffffu, d, o);
        if (lane == 0) out[e0 + j] = d;
    }
}

// ---------------- launch -----------------------------------------------------
extern "C" void kernel_launch(void* const* d_in, const int* in_sizes, int n_in,
                              void* d_out, int out_size) {
    const float* x   = (const float*)d_in[0];
    const float* W1l = (const float*)d_in[1];
    const float* b1  = (const float*)d_in[2];
    const float* W1r = (const float*)d_in[3];
    const float* W2l = (const float*)d_in[4];
    const float* b2  = (const float*)d_in[5];
    const float* W2r = (const float*)d_in[6];
    const int* edge_index = (const int*)d_in[7];
    const int* pred_edges = (const int*)d_in[8];
    float* out = (float*)d_out;

    const int* src = edge_index;
    const int* dst = edge_index + EE;
    const int* ps = pred_edges;
    const int* pd = pred_edges + EPP;

    static int attr_done = 0;
    if (!attr_done) {
        cudaFuncSetAttribute(k_mm, cudaFuncAttributeMaxDynamicSharedMemorySize, SMEM_MM);
        attr_done = 1;
    }

    k_init<<<(NN + 2 * DIM * KK + 255) / 256, 256>>>(W1l, W1r, W2l, W2r);
    k_count<<<(EE / 4 + 255) / 256, 256>>>(dst);
    k_scan1<<<NBLK, 1024>>>();
    k_scan2<<<1, 64>>>();
    k_scan3<<<(NN + 255) / 256, 256>>>();
    k_fill<<<(EE / 4 + 255) / 256, 256>>>(src, dst);

    k_agg<<<(NN * 32 + 255) / 256, 256>>>(x, 0);
    k_mm<<<MTILES, 256, SMEM_MM>>>(b1, 1);
    k_agg<<<(NN * 32 + 255) / 256, 256>>>(nullptr, 1);
    k_mm<<<MTILES, 256, SMEM_MM>>>(b2, 2);
    k_pred<<<(EPP / 4 * 32 + 255) / 256, 256>>>(ps, pd, out);
}